// round 14
// baseline (speedup 1.0000x reference)
#include <cuda_runtime.h>
#include <cuda_fp16.h>
#include <cstdint>

#define W_ 12
#define N_ 20000
#define C_ 64
#define E_ 320000
#define TOT (W_*N_*C_)   // 15,360,000
typedef unsigned long long ull;
typedef unsigned int uint;

// ---------------- scratch (device globals) ----------------------------------
__device__ __align__(128) __half g_WpH[7*128*64];          // inception weights, plain [t][n][64]
__device__ __align__(128) __half g_XpH[(size_t)W_*N_*64];  // x rows fp16, plain [(w,n)][64]
__device__ __align__(128) ull    g_Gwp[2*12*8*4*32];       // gcn weights [(hop,w)][nt][ks][lane]
__device__ __align__(128) float  g_bc[128];
__device__ __align__(128) __half g_Hh [TOT];               // h buffer, fp16 channel-order (W,N,C)
__device__ __align__(128) uint   g_AggU[(size_t)W_*N_*32]; // aggregated h, fp16 MMA-A packed
__device__ int  g_deg   [W_*N_];
__device__ int  g_rowptr[W_*N_];
__device__ int  g_cur   [W_*N_];
__device__ int2 g_edge  [W_*E_];   // {src, wt bits}

struct WPtrs {
    const float* sw[4]; const float* sb[4];
    const float* gw[4]; const float* gb[4];
};

// ---------------- helpers ----------------------------------------------------
__device__ __forceinline__ uint pack_h2(float a, float b) {
    __half2 h = __floats2half2_rn(a, b);
    return *(uint*)&h;
}
__device__ __forceinline__ void mma_f16(float (&c)[4], uint a0, uint a1, uint a2, uint a3,
                                        uint b0, uint b1) {
    asm volatile(
        "mma.sync.aligned.m16n8k16.row.col.f32.f16.f16.f32 "
        "{%0,%1,%2,%3}, {%4,%5,%6,%7}, {%8,%9}, {%0,%1,%2,%3};\n"
        : "+f"(c[0]), "+f"(c[1]), "+f"(c[2]), "+f"(c[3])
        : "r"(a0), "r"(a1), "r"(a2), "r"(a3), "r"(b0), "r"(b1));
}
__device__ __forceinline__ void ldm_x4(uint& r0, uint& r1, uint& r2, uint& r3, uint a) {
    asm volatile("ldmatrix.sync.aligned.m8n8.x4.shared.b16 {%0,%1,%2,%3}, [%4];"
        : "=r"(r0), "=r"(r1), "=r"(r2), "=r"(r3) : "r"(a));
}
__device__ __forceinline__ void ldm_x2(uint& r0, uint& r1, uint a) {
    asm volatile("ldmatrix.sync.aligned.m8n8.x2.shared.b16 {%0,%1}, [%2];"
        : "=r"(r0), "=r"(r1) : "r"(a));
}
__device__ __forceinline__ void cpasync16(void* sdst, const void* gsrc) {
    uint s = (uint)__cvta_generic_to_shared(sdst);
    asm volatile("cp.async.ca.shared.global [%0], [%1], 16;" :: "r"(s), "l"(gsrc));
}
__device__ __forceinline__ void cp_commit() { asm volatile("cp.async.commit_group;"); }
__device__ __forceinline__ void cp_wait0()  { asm volatile("cp.async.wait_group 0;"); }
__device__ __forceinline__ float elu1(float v) { return v > 0.f ? v : expm1f(v); }

// ---------------- K0: build plain fp16 inception weights + bias --------------
__global__ void prep_kernel(WPtrs p) {
    int gid = blockIdx.x * blockDim.x + threadIdx.x;
    if (gid < 7*128*64) {
        int t   = gid >> 13;           // 128*64 = 8192
        int rem = gid & 8191;
        int n   = rem >> 6, c = rem & 63;
        int kw  = n >> 5, half = (n >> 4) & 1, ch = n & 15, k = 2*kw + 1;
        int tt  = t - 3 + kw;
        float v = 0.f;
        if (tt >= 0 && tt < k)
            v = (half ? p.gw[kw] : p.sw[kw])[(ch*64 + c)*k + tt];
        g_WpH[gid] = __float2half(v);
    }
    if (gid < 128) {
        int j = gid;
        int kw = j >> 5; int half = (j >> 4) & 1; int ch = j & 15;
        g_bc[j] = half ? p.gb[kw][ch] : p.sb[kw][ch];
    }
}

// ---------------- K0c: pack gcn weights as MMA B-fragments -------------------
__global__ void prep_gw_kernel(const float* __restrict__ gw) {
    int gid = blockIdx.x*256 + threadIdx.x;
    if (gid >= 2*12*8*4*32) return;
    int lane = gid & 31;
    int ks   = (gid >> 5) & 3;
    int nt   = (gid >> 7) & 7;
    int rest = gid >> 10;            // hop*12 + w
    int n = nt*8 + (lane >> 2);
    int q = lane & 3;
    int k0 = ks*16 + 2*q;
    const float* Wb = gw + (size_t)rest*64*64;
    float v0 = Wb[(k0    )*64 + n];
    float v1 = Wb[(k0 + 1)*64 + n];
    float v2 = Wb[(k0 + 8)*64 + n];
    float v3 = Wb[(k0 + 9)*64 + n];
    g_Gwp[gid] = (ull)pack_h2(v0, v1) | ((ull)pack_h2(v2, v3) << 32);
}

// ---------------- K0b: pack x into plain fp16 rows ---------------------------
__global__ void pack_x_kernel(const float4* __restrict__ x4) {
    int gid = blockIdx.x*256 + threadIdx.x;
    if (gid >= W_*N_*8) return;
    int row = gid >> 3, c = gid & 7;
    float4 f0 = x4[(size_t)row*16 + c*2];
    float4 f1 = x4[(size_t)row*16 + c*2 + 1];
    uint4 o;
    o.x = pack_h2(f0.x, f0.y); o.y = pack_h2(f0.z, f0.w);
    o.z = pack_h2(f1.x, f1.y); o.w = pack_h2(f1.z, f1.w);
    ((uint4*)g_XpH)[(size_t)row*8 + c] = o;
}

// ---------------- K1: inception via fp16 mma + ldmatrix ----------------------
#define XROWB 144
#define XS_BYTES (18*16*XROWB)       // 41472
#define WS_BYTES (128*XROWB)         // 18432
#define SMEM_BYTES (XS_BYTES + 2*WS_BYTES)

__global__ void __launch_bounds__(256, 2) incep_mma_kernel() {
    extern __shared__ char sm[];
    char* Xs = sm;                    // [wi(18)][nloc(16)] rows
    char* Ws = sm + XS_BYTES;         // [2][n(128)] rows

    int tid = threadIdx.x;
    int n0  = blockIdx.x * 16;

    {
        const int zl[6] = {0,1,2,15,16,17};
        for (int idx = tid; idx < 6*16*9; idx += 256) {
            int r = idx / 9, c = idx - r*9;
            int wi = zl[r >> 4], nloc = r & 15;
            ((uint4*)(Xs + (wi*16 + nloc)*XROWB))[c] = make_uint4(0,0,0,0);
        }
    }
    for (int idx = tid; idx < 12*16*8; idx += 256) {
        int c = idx & 7, row = idx >> 3;
        int wrow = row >> 4, nloc = row & 15;
        cpasync16(Xs + ((wrow+3)*16 + nloc)*XROWB + c*16,
                  g_XpH + ((size_t)(wrow*N_ + n0 + nloc))*64 + c*8);
    }
    for (int idx = tid; idx < 128*8; idx += 256) {
        int c = idx & 7, n = idx >> 3;
        cpasync16(Ws + n*XROWB + c*16, g_WpH + ((size_t)n)*64 + c*8);
    }
    cp_commit();
    cp_wait0();
    __syncthreads();

    int lane = tid & 31, wid = tid >> 5;
    int mg = wid >> 1, par = wid & 1;
    int g = lane >> 2, q = lane & 3;

    uint xsB = (uint)__cvta_generic_to_shared(Xs);
    uint wsB = (uint)__cvta_generic_to_shared(Ws);
    uint aA0 = xsB + (lane & 15)*XROWB + (lane >> 4)*16;
    uint bA0 = wsB + (lane & 7)*XROWB + ((lane >> 3) & 1)*16;

    float acc[3][8][4];
    #pragma unroll
    for (int j = 0; j < 3; j++)
        #pragma unroll
        for (int u = 0; u < 8; u++)
            #pragma unroll
            for (int c = 0; c < 4; c++) acc[j][u][c] = 0.f;

    for (int t = 0; t < 7; t++) {
        if (t < 6) {
            char* Wn = Ws + ((t+1)&1)*WS_BYTES;
            for (int idx = tid; idx < 128*8; idx += 256) {
                int c = idx & 7, n = idx >> 3;
                cpasync16(Wn + n*XROWB + c*16, g_WpH + ((size_t)((t+1)*128 + n))*64 + c*8);
            }
            cp_commit();
        }
        uint wB = bA0 + (t&1)*WS_BYTES;
        uint aB = aA0 + (3*mg + t)*(16*XROWB);

        #pragma unroll
        for (int ks = 0; ks < 4; ks++) {
            uint a0[3], a1[3], a2[3], a3[3];
            #pragma unroll
            for (int j = 0; j < 3; j++)
                ldm_x4(a0[j], a1[j], a2[j], a3[j], aB + j*(16*XROWB) + ks*32);
            #pragma unroll
            for (int u = 0; u < 8; u++) {
                int nt = 2*u + par;
                int kw = nt >> 2;
                if (t >= 3-kw && t <= 3+kw) {
                    uint b0, b1;
                    ldm_x2(b0, b1, wB + nt*(8*XROWB) + ks*32);
                    mma_f16(acc[0][u], a0[0], a1[0], a2[0], a3[0], b0, b1);
                    mma_f16(acc[1][u], a0[1], a1[1], a2[1], a3[1], b0, b1);
                    mma_f16(acc[2][u], a0[2], a1[2], a2[2], a3[2], b0, b1);
                }
            }
        }
        if (t < 6) cp_wait0();
        __syncthreads();
    }

    #pragma unroll
    for (int j = 0; j < 3; j++) {
        int w = 3*mg + j;
        #pragma unroll
        for (int us = 0; us < 8; us += 2) {
            int nts = 2*us + par;
            float2 bs = *(const float2*)&g_bc[nts*8 + 2*q];
            float2 bg = *(const float2*)&g_bc[(nts+2)*8 + 2*q];
            float s0 = acc[j][us][0] + bs.x, s1 = acc[j][us][1] + bs.y;
            float s2 = acc[j][us][2] + bs.x, s3 = acc[j][us][3] + bs.y;
            float g0 = acc[j][us+1][0] + bg.x, g1 = acc[j][us+1][1] + bg.y;
            float g2 = acc[j][us+1][2] + bg.x, g3 = acc[j][us+1][3] + bg.y;
            float o0 = fmaxf(s0, 0.f) * (1.f/(1.f + __expf(-g0)));
            float o1 = fmaxf(s1, 0.f) * (1.f/(1.f + __expf(-g1)));
            float o2 = fmaxf(s2, 0.f) * (1.f/(1.f + __expf(-g2)));
            float o3 = fmaxf(s3, 0.f) * (1.f/(1.f + __expf(-g3)));
            int kw = nts >> 2;
            int cout = kw*16 + par*8 + 2*q;
            *(__half2*)&g_Hh[((size_t)w*N_ + n0 + g    )*64 + cout] = __floats2half2_rn(o0, o1);
            *(__half2*)&g_Hh[((size_t)w*N_ + n0 + g + 8)*64 + cout] = __floats2half2_rn(o2, o3);
        }
    }
}

// ---------------- CSR build (once), 4 edges/thread ---------------------------
__global__ void hist_kernel(const int* __restrict__ ei) {
    int g = blockIdx.x*blockDim.x + threadIdx.x;
    if (g >= W_*E_/4) return;
    int w  = g / (E_/4);
    int e4 = (g - w*(E_/4))*4;
    int4 d = *(const int4*)&ei[(size_t)(2*w+1)*E_ + e4];
    atomicAdd(&g_deg[w*N_ + d.x], 1);
    atomicAdd(&g_deg[w*N_ + d.y], 1);
    atomicAdd(&g_deg[w*N_ + d.z], 1);
    atomicAdd(&g_deg[w*N_ + d.w], 1);
}

__global__ void __launch_bounds__(512) scan_kernel() {
    __shared__ int wsum[16];
    int w = blockIdx.x;
    int t = threadIdx.x, lane = t & 31, wid = t >> 5;
    const int* deg = g_deg + w*N_;
    int base = t * 40;
    int s = 0;
    for (int k = 0; k < 40; k++) {
        int idx = base + k;
        if (idx < N_) s += deg[idx];
    }
    int v = s;
    #pragma unroll
    for (int d = 1; d < 32; d <<= 1) {
        int o = __shfl_up_sync(0xffffffffu, v, d);
        if (lane >= d) v += o;
    }
    if (lane == 31) wsum[wid] = v;
    __syncthreads();
    if (t == 0) {
        int r = 0;
        #pragma unroll
        for (int qq = 0; qq < 16; qq++) { int xq = wsum[qq]; wsum[qq] = r; r += xq; }
    }
    __syncthreads();
    int run = wsum[wid] + (v - s);
    for (int k = 0; k < 40; k++) {
        int idx = base + k;
        if (idx < N_) {
            int d = deg[idx];
            g_rowptr[w*N_ + idx] = run;
            g_cur   [w*N_ + idx] = run;
            run += d;
        }
    }
}

__global__ void place_kernel(const int* __restrict__ ei, const float* __restrict__ ewt) {
    int g = blockIdx.x*blockDim.x + threadIdx.x;
    if (g >= W_*E_/4) return;
    int w  = g / (E_/4);
    int e4 = (g - w*(E_/4))*4;
    int4   s = *(const int4*)  &ei [(size_t)(2*w)  *E_ + e4];
    int4   d = *(const int4*)  &ei [(size_t)(2*w+1)*E_ + e4];
    float4 t = *(const float4*)&ewt[(size_t)w*E_ + e4];
    int2* eb = g_edge + (size_t)w*E_;
    int* cur = g_cur + w*N_;
    int p0 = atomicAdd(&cur[d.x], 1);
    int p1 = atomicAdd(&cur[d.y], 1);
    int p2 = atomicAdd(&cur[d.z], 1);
    int p3 = atomicAdd(&cur[d.w], 1);
    eb[p0] = make_int2(s.x, __float_as_int(t.x));
    eb[p1] = make_int2(s.y, __float_as_int(t.y));
    eb[p2] = make_int2(s.z, __float_as_int(t.z));
    eb[p3] = make_int2(s.w, __float_as_int(t.w));
}

// ---------------- K4: gather-aggregate, warp-per-node ------------------------
// One warp owns one node: lane holds channels (2*lane, 2*lane+1). Edge batch of
// 32 loaded coalesced; fully-unrolled predicated j-loop keeps up to 32
// independent LDG.32 gathers in flight; warp-uniform trip count (no divergence).
__global__ void __launch_bounds__(256) agg_kernel() {
    int wn   = blockIdx.x*8 + (threadIdx.x >> 5);   // node index over W*N
    int lane = threadIdx.x & 31;
    int w    = wn / N_;

    int beg = g_rowptr[wn];
    int deg = g_deg[wn];
    const int2* ed = g_edge + (size_t)w*E_;
    const uint* Hb = (const uint*)g_Hh + ((size_t)w*N_)*32 + lane;

    float a0 = 0.f, a1 = 0.f;
    for (int base = 0; base < deg; base += 32) {
        int m = deg - base; if (m > 32) m = 32;
        int2 pr = make_int2(0, 0);
        if (lane < m) pr = ed[beg + base + lane];
        #pragma unroll
        for (int j = 0; j < 32; j++) {
            if (j < m) {
                int   src = __shfl_sync(0xffffffffu, pr.x, j);
                float wt  = __int_as_float(__shfl_sync(0xffffffffu, pr.y, j));
                uint  v   = Hb[(size_t)src*32];
                float2 f = __half22float2(*(__half2*)&v);
                a0 = fmaf(wt, f.x, a0);
                a1 = fmaf(wt, f.y, a1);
            }
        }
    }
    // packed-A word-half for channels (2l, 2l+1):
    // ks = l>>3; rem = 2l & 15; hi = rem>=8; qq = (rem&7)>>1
    int c0 = 2*lane;
    int ks = lane >> 3;
    int rem = c0 & 15;
    int hi = (rem >= 8) ? 1 : 0;
    int qq = (rem & 7) >> 1;
    g_AggU[(size_t)wn*32 + (ks*4 + qq)*2 + hi] = pack_h2(a0, a1);
}

// ---------------- K5: tensor-core gemm + bias + ELU (+residual) -------------
__global__ void __launch_bounds__(256) gemm_mma_kernel(const float* __restrict__ gb, int hop,
                                                       const float* __restrict__ x,
                                                       float* __restrict__ out) {
    int w = blockIdx.y;
    int wid = threadIdx.x >> 5, lane = threadIdx.x & 31;
    int g = lane >> 2, q = lane & 3;
    int n0 = blockIdx.x*256 + wid*32;
    if (n0 >= N_) return;

    const ull* A  = (const ull*)g_AggU + (size_t)w*N_*16;
    const ull* Wm = g_Gwp + ((size_t)(hop*W_ + w))*8*4*32;
    const float* bias = gb + (size_t)(hop*W_ + w)*64;

    float acc[2][8][4];
    #pragma unroll
    for (int nt = 0; nt < 8; nt++) {
        float2 bv = *(const float2*)&bias[nt*8 + 2*q];
        #pragma unroll
        for (int mt = 0; mt < 2; mt++) {
            acc[mt][nt][0] = bv.x; acc[mt][nt][1] = bv.y;
            acc[mt][nt][2] = bv.x; acc[mt][nt][3] = bv.y;
        }
    }

    int r0 = n0 + g, r1 = n0 + g + 8, r2 = n0 + 16 + g, r3 = n0 + 24 + g;
    #pragma unroll
    for (int ks = 0; ks < 4; ks++) {
        int kk = ks*4 + q;
        ull v0 = (r0 < N_) ? A[(size_t)r0*16 + kk] : 0ull;
        ull v1 = (r1 < N_) ? A[(size_t)r1*16 + kk] : 0ull;
        ull v2 = (r2 < N_) ? A[(size_t)r2*16 + kk] : 0ull;
        ull v3 = (r3 < N_) ? A[(size_t)r3*16 + kk] : 0ull;
        uint a00 = (uint)v0, a02 = (uint)(v0 >> 32);
        uint a01 = (uint)v1, a03 = (uint)(v1 >> 32);
        uint a10 = (uint)v2, a12 = (uint)(v2 >> 32);
        uint a11 = (uint)v3, a13 = (uint)(v3 >> 32);
        #pragma unroll
        for (int nt = 0; nt < 8; nt++) {
            ull bw = Wm[(nt*4 + ks)*32 + lane];
            uint b0 = (uint)bw, b1 = (uint)(bw >> 32);
            mma_f16(acc[0][nt], a00, a01, a02, a03, b0, b1);
            mma_f16(acc[1][nt], a10, a11, a12, a13, b0, b1);
        }
    }

    #pragma unroll
    for (int mt = 0; mt < 2; mt++) {
        int rA = n0 + mt*16 + g, rB = rA + 8;
        #pragma unroll
        for (int nt = 0; nt < 8; nt++) {
            float c0 = elu1(acc[mt][nt][0]);
            float c1 = elu1(acc[mt][nt][1]);
            float c2 = elu1(acc[mt][nt][2]);
            float c3 = elu1(acc[mt][nt][3]);
            int cout0 = nt*8 + 2*q;
            if (out) {
                if (rA < N_) {
                    size_t oi = ((size_t)w*N_ + rA)*64 + cout0;
                    float2 xv = *(const float2*)&x[oi];
                    *(float2*)&out[oi] = make_float2(c0 + xv.x, c1 + xv.y);
                }
                if (rB < N_) {
                    size_t oi = ((size_t)w*N_ + rB)*64 + cout0;
                    float2 xv = *(const float2*)&x[oi];
                    *(float2*)&out[oi] = make_float2(c2 + xv.x, c3 + xv.y);
                }
            } else {
                if (rA < N_)
                    *(__half2*)&g_Hh[((size_t)w*N_ + rA)*64 + cout0] = __floats2half2_rn(c0, c1);
                if (rB < N_)
                    *(__half2*)&g_Hh[((size_t)w*N_ + rB)*64 + cout0] = __floats2half2_rn(c2, c3);
            }
        }
    }
}

// ---------------- launch -----------------------------------------------------
extern "C" void kernel_launch(void* const* d_in, const int* in_sizes, int n_in,
                              void* d_out, int out_size) {
    const float* x  = (const float*)d_in[0];
    const int*   ei = (const int*)  d_in[1];
    const float* ew = (const float*)d_in[2];

    WPtrs p;
    if (in_sizes[5] == 1024) {
        int idx = 3;
        for (int t = 0; t < 4; t++) {
            p.sw[t] = (const float*)d_in[idx++];
            p.sb[t] = (const float*)d_in[idx++];
            p.gw[t] = (const float*)d_in[idx++];
            p.gb[t] = (const float*)d_in[idx++];
        }
    } else {
        int idx = 3;
        for (int t = 0; t < 4; t++) {
            p.sw[t] = (const float*)d_in[idx++];
            p.sb[t] = (const float*)d_in[idx++];
        }
        for (int t = 0; t < 4; t++) {
            p.gw[t] = (const float*)d_in[idx++];
            p.gb[t] = (const float*)d_in[idx++];
        }
    }
    const float* gw = (const float*)d_in[19];
    const float* gb = (const float*)d_in[20];
    float* out = (float*)d_out;

    static cudaStream_t s2 = nullptr;
    static cudaEvent_t evA = nullptr, evB = nullptr;
    static int* degPtr = nullptr;
    if (!s2) {
        cudaFuncSetAttribute(incep_mma_kernel,
                             cudaFuncAttributeMaxDynamicSharedMemorySize, SMEM_BYTES);
        cudaStreamCreateWithFlags(&s2, cudaStreamNonBlocking);
        cudaEventCreateWithFlags(&evA, cudaEventDisableTiming);
        cudaEventCreateWithFlags(&evB, cudaEventDisableTiming);
        cudaGetSymbolAddress((void**)&degPtr, g_deg);
    }

    // fork: CSR build on s2, inception chain on main stream
    cudaEventRecord(evA, 0);
    cudaStreamWaitEvent(s2, evA, 0);

    cudaMemsetAsync(degPtr, 0, W_*N_*sizeof(int), s2);
    hist_kernel<<<(W_*E_/4 + 255)/256, 256, 0, s2>>>(ei);
    scan_kernel<<<W_, 512, 0, s2>>>();
    place_kernel<<<(W_*E_/4 + 255)/256, 256, 0, s2>>>(ei, ew);
    cudaEventRecord(evB, s2);

    prep_kernel<<<(7*128*64 + 255)/256, 256>>>(p);
    prep_gw_kernel<<<(2*12*8*4*32 + 255)/256, 256>>>(gw);
    pack_x_kernel<<<(W_*N_*8 + 255)/256, 256>>>((const float4*)x);
    incep_mma_kernel<<<N_/16, 256, SMEM_BYTES>>>();

    // join
    cudaStreamWaitEvent(0, evB, 0);

    for (int hop = 0; hop < 2; hop++) {
        agg_kernel<<<W_*N_/8, 256>>>();
        gemm_mma_kernel<<<dim3((N_ + 255)/256, W_), 256>>>(gb, hop, x,
                                                           hop == 1 ? out : nullptr);
    }
}

// round 15
// speedup vs baseline: 1.2622x; 1.2622x over previous
#include <cuda_runtime.h>
#include <cuda_fp16.h>
#include <cstdint>

#define W_ 12
#define N_ 20000
#define C_ 64
#define E_ 320000
#define TOT (W_*N_*C_)   // 15,360,000
typedef unsigned long long ull;
typedef unsigned int uint;

// ---------------- scratch (device globals) ----------------------------------
__device__ __align__(128) __half g_WpH[7*128*64];          // inception weights, plain [t][n][64]
__device__ __align__(128) __half g_XpH[(size_t)W_*N_*64];  // x rows fp16, plain [(w,n)][64]
__device__ __align__(128) ull    g_Gwp[2*12*8*4*32];       // gcn weights [(hop,w)][nt][ks][lane]
__device__ __align__(128) float  g_bc[128];
__device__ __align__(128) __half g_Hh [TOT];               // h buffer, fp16 channel-order (W,N,C)
__device__ __align__(128) uint   g_AggU[(size_t)W_*N_*32]; // aggregated h, fp16 MMA-A packed
__device__ int  g_deg   [W_*N_];
__device__ int  g_rowptr[W_*N_];
__device__ int  g_cur   [W_*N_];
__device__ int2 g_edge  [W_*E_];   // {src, wt bits}
__device__ int  g_bhist [64];      // degree-bucket histogram
__device__ int  g_bcur  [64];      // degree-bucket cursors
__device__ int  g_ord   [W_*N_];   // nodes sorted by degree bucket

struct WPtrs {
    const float* sw[4]; const float* sb[4];
    const float* gw[4]; const float* gb[4];
};

// ---------------- helpers ----------------------------------------------------
__device__ __forceinline__ uint pack_h2(float a, float b) {
    __half2 h = __floats2half2_rn(a, b);
    return *(uint*)&h;
}
__device__ __forceinline__ void mma_f16(float (&c)[4], uint a0, uint a1, uint a2, uint a3,
                                        uint b0, uint b1) {
    asm volatile(
        "mma.sync.aligned.m16n8k16.row.col.f32.f16.f16.f32 "
        "{%0,%1,%2,%3}, {%4,%5,%6,%7}, {%8,%9}, {%0,%1,%2,%3};\n"
        : "+f"(c[0]), "+f"(c[1]), "+f"(c[2]), "+f"(c[3])
        : "r"(a0), "r"(a1), "r"(a2), "r"(a3), "r"(b0), "r"(b1));
}
__device__ __forceinline__ void ldm_x4(uint& r0, uint& r1, uint& r2, uint& r3, uint a) {
    asm volatile("ldmatrix.sync.aligned.m8n8.x4.shared.b16 {%0,%1,%2,%3}, [%4];"
        : "=r"(r0), "=r"(r1), "=r"(r2), "=r"(r3) : "r"(a));
}
__device__ __forceinline__ void ldm_x2(uint& r0, uint& r1, uint a) {
    asm volatile("ldmatrix.sync.aligned.m8n8.x2.shared.b16 {%0,%1}, [%2];"
        : "=r"(r0), "=r"(r1) : "r"(a));
}
__device__ __forceinline__ void cpasync16(void* sdst, const void* gsrc) {
    uint s = (uint)__cvta_generic_to_shared(sdst);
    asm volatile("cp.async.ca.shared.global [%0], [%1], 16;" :: "r"(s), "l"(gsrc));
}
__device__ __forceinline__ void cp_commit() { asm volatile("cp.async.commit_group;"); }
__device__ __forceinline__ void cp_wait0()  { asm volatile("cp.async.wait_group 0;"); }
__device__ __forceinline__ float elu1(float v) { return v > 0.f ? v : expm1f(v); }

// ---------------- K0: build plain fp16 inception weights + bias --------------
__global__ void prep_kernel(WPtrs p) {
    int gid = blockIdx.x * blockDim.x + threadIdx.x;
    if (gid < 7*128*64) {
        int t   = gid >> 13;           // 128*64 = 8192
        int rem = gid & 8191;
        int n   = rem >> 6, c = rem & 63;
        int kw  = n >> 5, half = (n >> 4) & 1, ch = n & 15, k = 2*kw + 1;
        int tt  = t - 3 + kw;
        float v = 0.f;
        if (tt >= 0 && tt < k)
            v = (half ? p.gw[kw] : p.sw[kw])[(ch*64 + c)*k + tt];
        g_WpH[gid] = __float2half(v);
    }
    if (gid < 128) {
        int j = gid;
        int kw = j >> 5; int half = (j >> 4) & 1; int ch = j & 15;
        g_bc[j] = half ? p.gb[kw][ch] : p.sb[kw][ch];
    }
}

// ---------------- K0c: pack gcn weights as MMA B-fragments -------------------
__global__ void prep_gw_kernel(const float* __restrict__ gw) {
    int gid = blockIdx.x*256 + threadIdx.x;
    if (gid >= 2*12*8*4*32) return;
    int lane = gid & 31;
    int ks   = (gid >> 5) & 3;
    int nt   = (gid >> 7) & 7;
    int rest = gid >> 10;            // hop*12 + w
    int n = nt*8 + (lane >> 2);
    int q = lane & 3;
    int k0 = ks*16 + 2*q;
    const float* Wb = gw + (size_t)rest*64*64;
    float v0 = Wb[(k0    )*64 + n];
    float v1 = Wb[(k0 + 1)*64 + n];
    float v2 = Wb[(k0 + 8)*64 + n];
    float v3 = Wb[(k0 + 9)*64 + n];
    g_Gwp[gid] = (ull)pack_h2(v0, v1) | ((ull)pack_h2(v2, v3) << 32);
}

// ---------------- K0b: pack x into plain fp16 rows ---------------------------
__global__ void pack_x_kernel(const float4* __restrict__ x4) {
    int gid = blockIdx.x*256 + threadIdx.x;
    if (gid >= W_*N_*8) return;
    int row = gid >> 3, c = gid & 7;
    float4 f0 = x4[(size_t)row*16 + c*2];
    float4 f1 = x4[(size_t)row*16 + c*2 + 1];
    uint4 o;
    o.x = pack_h2(f0.x, f0.y); o.y = pack_h2(f0.z, f0.w);
    o.z = pack_h2(f1.x, f1.y); o.w = pack_h2(f1.z, f1.w);
    ((uint4*)g_XpH)[(size_t)row*8 + c] = o;
}

// ---------------- K1: inception via fp16 mma + ldmatrix ----------------------
#define XROWB 144
#define XS_BYTES (18*16*XROWB)       // 41472
#define WS_BYTES (128*XROWB)         // 18432
#define SMEM_BYTES (XS_BYTES + 2*WS_BYTES)

__global__ void __launch_bounds__(256, 2) incep_mma_kernel() {
    extern __shared__ char sm[];
    char* Xs = sm;                    // [wi(18)][nloc(16)] rows
    char* Ws = sm + XS_BYTES;         // [2][n(128)] rows

    int tid = threadIdx.x;
    int n0  = blockIdx.x * 16;

    {
        const int zl[6] = {0,1,2,15,16,17};
        for (int idx = tid; idx < 6*16*9; idx += 256) {
            int r = idx / 9, c = idx - r*9;
            int wi = zl[r >> 4], nloc = r & 15;
            ((uint4*)(Xs + (wi*16 + nloc)*XROWB))[c] = make_uint4(0,0,0,0);
        }
    }
    for (int idx = tid; idx < 12*16*8; idx += 256) {
        int c = idx & 7, row = idx >> 3;
        int wrow = row >> 4, nloc = row & 15;
        cpasync16(Xs + ((wrow+3)*16 + nloc)*XROWB + c*16,
                  g_XpH + ((size_t)(wrow*N_ + n0 + nloc))*64 + c*8);
    }
    for (int idx = tid; idx < 128*8; idx += 256) {
        int c = idx & 7, n = idx >> 3;
        cpasync16(Ws + n*XROWB + c*16, g_WpH + ((size_t)n)*64 + c*8);
    }
    cp_commit();
    cp_wait0();
    __syncthreads();

    int lane = tid & 31, wid = tid >> 5;
    int mg = wid >> 1, par = wid & 1;
    int g = lane >> 2, q = lane & 3;

    uint xsB = (uint)__cvta_generic_to_shared(Xs);
    uint wsB = (uint)__cvta_generic_to_shared(Ws);
    uint aA0 = xsB + (lane & 15)*XROWB + (lane >> 4)*16;
    uint bA0 = wsB + (lane & 7)*XROWB + ((lane >> 3) & 1)*16;

    float acc[3][8][4];
    #pragma unroll
    for (int j = 0; j < 3; j++)
        #pragma unroll
        for (int u = 0; u < 8; u++)
            #pragma unroll
            for (int c = 0; c < 4; c++) acc[j][u][c] = 0.f;

    for (int t = 0; t < 7; t++) {
        if (t < 6) {
            char* Wn = Ws + ((t+1)&1)*WS_BYTES;
            for (int idx = tid; idx < 128*8; idx += 256) {
                int c = idx & 7, n = idx >> 3;
                cpasync16(Wn + n*XROWB + c*16, g_WpH + ((size_t)((t+1)*128 + n))*64 + c*8);
            }
            cp_commit();
        }
        uint wB = bA0 + (t&1)*WS_BYTES;
        uint aB = aA0 + (3*mg + t)*(16*XROWB);

        #pragma unroll
        for (int ks = 0; ks < 4; ks++) {
            uint a0[3], a1[3], a2[3], a3[3];
            #pragma unroll
            for (int j = 0; j < 3; j++)
                ldm_x4(a0[j], a1[j], a2[j], a3[j], aB + j*(16*XROWB) + ks*32);
            #pragma unroll
            for (int u = 0; u < 8; u++) {
                int nt = 2*u + par;
                int kw = nt >> 2;
                if (t >= 3-kw && t <= 3+kw) {
                    uint b0, b1;
                    ldm_x2(b0, b1, wB + nt*(8*XROWB) + ks*32);
                    mma_f16(acc[0][u], a0[0], a1[0], a2[0], a3[0], b0, b1);
                    mma_f16(acc[1][u], a0[1], a1[1], a2[1], a3[1], b0, b1);
                    mma_f16(acc[2][u], a0[2], a1[2], a2[2], a3[2], b0, b1);
                }
            }
        }
        if (t < 6) cp_wait0();
        __syncthreads();
    }

    #pragma unroll
    for (int j = 0; j < 3; j++) {
        int w = 3*mg + j;
        #pragma unroll
        for (int us = 0; us < 8; us += 2) {
            int nts = 2*us + par;
            float2 bs = *(const float2*)&g_bc[nts*8 + 2*q];
            float2 bg = *(const float2*)&g_bc[(nts+2)*8 + 2*q];
            float s0 = acc[j][us][0] + bs.x, s1 = acc[j][us][1] + bs.y;
            float s2 = acc[j][us][2] + bs.x, s3 = acc[j][us][3] + bs.y;
            float g0 = acc[j][us+1][0] + bg.x, g1 = acc[j][us+1][1] + bg.y;
            float g2 = acc[j][us+1][2] + bg.x, g3 = acc[j][us+1][3] + bg.y;
            float o0 = fmaxf(s0, 0.f) * (1.f/(1.f + __expf(-g0)));
            float o1 = fmaxf(s1, 0.f) * (1.f/(1.f + __expf(-g1)));
            float o2 = fmaxf(s2, 0.f) * (1.f/(1.f + __expf(-g2)));
            float o3 = fmaxf(s3, 0.f) * (1.f/(1.f + __expf(-g3)));
            int kw = nts >> 2;
            int cout = kw*16 + par*8 + 2*q;
            *(__half2*)&g_Hh[((size_t)w*N_ + n0 + g    )*64 + cout] = __floats2half2_rn(o0, o1);
            *(__half2*)&g_Hh[((size_t)w*N_ + n0 + g + 8)*64 + cout] = __floats2half2_rn(o2, o3);
        }
    }
}

// ---------------- CSR build (once), 4 edges/thread ---------------------------
__global__ void hist_kernel(const int* __restrict__ ei) {
    int g = blockIdx.x*blockDim.x + threadIdx.x;
    if (g >= W_*E_/4) return;
    int w  = g / (E_/4);
    int e4 = (g - w*(E_/4))*4;
    int4 d = *(const int4*)&ei[(size_t)(2*w+1)*E_ + e4];
    atomicAdd(&g_deg[w*N_ + d.x], 1);
    atomicAdd(&g_deg[w*N_ + d.y], 1);
    atomicAdd(&g_deg[w*N_ + d.z], 1);
    atomicAdd(&g_deg[w*N_ + d.w], 1);
}

__global__ void __launch_bounds__(512) scan_kernel() {
    __shared__ int wsum[16];
    int w = blockIdx.x;
    int t = threadIdx.x, lane = t & 31, wid = t >> 5;
    const int* deg = g_deg + w*N_;
    int base = t * 40;
    int s = 0;
    for (int k = 0; k < 40; k++) {
        int idx = base + k;
        if (idx < N_) s += deg[idx];
    }
    int v = s;
    #pragma unroll
    for (int d = 1; d < 32; d <<= 1) {
        int o = __shfl_up_sync(0xffffffffu, v, d);
        if (lane >= d) v += o;
    }
    if (lane == 31) wsum[wid] = v;
    __syncthreads();
    if (t == 0) {
        int r = 0;
        #pragma unroll
        for (int qq = 0; qq < 16; qq++) { int xq = wsum[qq]; wsum[qq] = r; r += xq; }
    }
    __syncthreads();
    int run = wsum[wid] + (v - s);
    for (int k = 0; k < 40; k++) {
        int idx = base + k;
        if (idx < N_) {
            int d = deg[idx];
            g_rowptr[w*N_ + idx] = run;
            g_cur   [w*N_ + idx] = run;
            run += d;
        }
    }
}

__global__ void place_kernel(const int* __restrict__ ei, const float* __restrict__ ewt) {
    int g = blockIdx.x*blockDim.x + threadIdx.x;
    if (g >= W_*E_/4) return;
    int w  = g / (E_/4);
    int e4 = (g - w*(E_/4))*4;
    int4   s = *(const int4*)  &ei [(size_t)(2*w)  *E_ + e4];
    int4   d = *(const int4*)  &ei [(size_t)(2*w+1)*E_ + e4];
    float4 t = *(const float4*)&ewt[(size_t)w*E_ + e4];
    int2* eb = g_edge + (size_t)w*E_;
    int* cur = g_cur + w*N_;
    int p0 = atomicAdd(&cur[d.x], 1);
    int p1 = atomicAdd(&cur[d.y], 1);
    int p2 = atomicAdd(&cur[d.z], 1);
    int p3 = atomicAdd(&cur[d.w], 1);
    eb[p0] = make_int2(s.x, __float_as_int(t.x));
    eb[p1] = make_int2(s.y, __float_as_int(t.y));
    eb[p2] = make_int2(s.z, __float_as_int(t.z));
    eb[p3] = make_int2(s.w, __float_as_int(t.w));
}

// ---------------- degree-bucket counting sort (s2 stream, overlapped) --------
__global__ void bhist_kernel() {
    __shared__ int lh[64];
    int t = threadIdx.x;
    if (t < 64) lh[t] = 0;
    __syncthreads();
    int i = blockIdx.x*256 + t;
    if (i < W_*N_) {
        int b = g_deg[i]; if (b > 63) b = 63;
        atomicAdd(&lh[b], 1);
    }
    __syncthreads();
    if (t < 64 && lh[t]) atomicAdd(&g_bhist[t], lh[t]);
}

__global__ void bscan_kernel() {   // 1 block, 64 threads
    __shared__ int tmp[64];
    int t = threadIdx.x;
    tmp[t] = g_bhist[t];
    __syncthreads();
    if (t == 0) {
        int r = 0;
        for (int i = 0; i < 64; i++) { int v = tmp[i]; tmp[i] = r; r += v; }
    }
    __syncthreads();
    g_bcur[t] = tmp[t];
}

__global__ void bplace_kernel() {
    int i = blockIdx.x*256 + threadIdx.x;
    if (i >= W_*N_) return;
    int b = g_deg[i]; if (b > 63) b = 63;
    int pos = atomicAdd(&g_bcur[b], 1);
    g_ord[pos] = i;
}

// ---------------- K4: gather-aggregate, degree-sorted, batch-16 --------------
__global__ void __launch_bounds__(256) agg_kernel() {
    int gid = blockIdx.x*256 + threadIdx.x;
    int q   = gid & 7;          // 8-channel slice
    int wn  = g_ord[gid >> 3];  // degree-sorted node id
    int w   = wn / N_;
    int lane = threadIdx.x & 31;
    uint gmask = 0xffu << (lane & 24);

    int beg = g_rowptr[wn];
    int deg = g_deg[wn];
    const int2*  ed = g_edge + (size_t)w*E_;
    const uint4* Hb = (const uint4*)g_Hh + (size_t)w*N_*8 + q;

    float a0=0.f,a1=0.f,a2=0.f,a3=0.f,a4=0.f,a5=0.f,a6=0.f,a7=0.f;
    for (int base = 0; base < deg; base += 16) {
        int lim = deg - base;
        int2 pr0 = make_int2(0, 0), pr1 = make_int2(0, 0);
        if (q     < lim) pr0 = ed[beg + base + q];
        if (q + 8 < lim) pr1 = ed[beg + base + 8 + q];
        int m = lim < 16 ? lim : 16;
        #pragma unroll
        for (int j = 0; j < 16; j++) {
            if (j < m) {
                int   src = __shfl_sync(gmask, j < 8 ? pr0.x : pr1.x, j & 7, 8);
                float wt  = __int_as_float(__shfl_sync(gmask, j < 8 ? pr0.y : pr1.y, j & 7, 8));
                uint4 v = Hb[(size_t)src*8];
                const __half2* hp = (const __half2*)&v;
                float2 f0 = __half22float2(hp[0]);
                float2 f1 = __half22float2(hp[1]);
                float2 f2 = __half22float2(hp[2]);
                float2 f3 = __half22float2(hp[3]);
                a0 = fmaf(wt, f0.x, a0); a1 = fmaf(wt, f0.y, a1);
                a2 = fmaf(wt, f1.x, a2); a3 = fmaf(wt, f1.y, a3);
                a4 = fmaf(wt, f2.x, a4); a5 = fmaf(wt, f2.y, a5);
                a6 = fmaf(wt, f3.x, a6); a7 = fmaf(wt, f3.y, a7);
            }
        }
    }
    int s = q >> 1, odd = q & 1;
    uint* o = g_AggU + (size_t)wn*32;
    o[(s*4 + 0)*2 + odd] = pack_h2(a0, a1);
    o[(s*4 + 1)*2 + odd] = pack_h2(a2, a3);
    o[(s*4 + 2)*2 + odd] = pack_h2(a4, a5);
    o[(s*4 + 3)*2 + odd] = pack_h2(a6, a7);
}

// ---------------- K5: tensor-core gemm + bias + ELU (+residual) -------------
__global__ void __launch_bounds__(256) gemm_mma_kernel(const float* __restrict__ gb, int hop,
                                                       const float* __restrict__ x,
                                                       float* __restrict__ out) {
    int w = blockIdx.y;
    int wid = threadIdx.x >> 5, lane = threadIdx.x & 31;
    int g = lane >> 2, q = lane & 3;
    int n0 = blockIdx.x*256 + wid*32;
    if (n0 >= N_) return;

    const ull* A  = (const ull*)g_AggU + (size_t)w*N_*16;
    const ull* Wm = g_Gwp + ((size_t)(hop*W_ + w))*8*4*32;
    const float* bias = gb + (size_t)(hop*W_ + w)*64;

    float acc[2][8][4];
    #pragma unroll
    for (int nt = 0; nt < 8; nt++) {
        float2 bv = *(const float2*)&bias[nt*8 + 2*q];
        #pragma unroll
        for (int mt = 0; mt < 2; mt++) {
            acc[mt][nt][0] = bv.x; acc[mt][nt][1] = bv.y;
            acc[mt][nt][2] = bv.x; acc[mt][nt][3] = bv.y;
        }
    }

    int r0 = n0 + g, r1 = n0 + g + 8, r2 = n0 + 16 + g, r3 = n0 + 24 + g;
    #pragma unroll
    for (int ks = 0; ks < 4; ks++) {
        int kk = ks*4 + q;
        ull v0 = (r0 < N_) ? A[(size_t)r0*16 + kk] : 0ull;
        ull v1 = (r1 < N_) ? A[(size_t)r1*16 + kk] : 0ull;
        ull v2 = (r2 < N_) ? A[(size_t)r2*16 + kk] : 0ull;
        ull v3 = (r3 < N_) ? A[(size_t)r3*16 + kk] : 0ull;
        uint a00 = (uint)v0, a02 = (uint)(v0 >> 32);
        uint a01 = (uint)v1, a03 = (uint)(v1 >> 32);
        uint a10 = (uint)v2, a12 = (uint)(v2 >> 32);
        uint a11 = (uint)v3, a13 = (uint)(v3 >> 32);
        #pragma unroll
        for (int nt = 0; nt < 8; nt++) {
            ull bw = Wm[(nt*4 + ks)*32 + lane];
            uint b0 = (uint)bw, b1 = (uint)(bw >> 32);
            mma_f16(acc[0][nt], a00, a01, a02, a03, b0, b1);
            mma_f16(acc[1][nt], a10, a11, a12, a13, b0, b1);
        }
    }

    #pragma unroll
    for (int mt = 0; mt < 2; mt++) {
        int rA = n0 + mt*16 + g, rB = rA + 8;
        #pragma unroll
        for (int nt = 0; nt < 8; nt++) {
            float c0 = elu1(acc[mt][nt][0]);
            float c1 = elu1(acc[mt][nt][1]);
            float c2 = elu1(acc[mt][nt][2]);
            float c3 = elu1(acc[mt][nt][3]);
            int cout0 = nt*8 + 2*q;
            if (out) {
                if (rA < N_) {
                    size_t oi = ((size_t)w*N_ + rA)*64 + cout0;
                    float2 xv = *(const float2*)&x[oi];
                    *(float2*)&out[oi] = make_float2(c0 + xv.x, c1 + xv.y);
                }
                if (rB < N_) {
                    size_t oi = ((size_t)w*N_ + rB)*64 + cout0;
                    float2 xv = *(const float2*)&x[oi];
                    *(float2*)&out[oi] = make_float2(c2 + xv.x, c3 + xv.y);
                }
            } else {
                if (rA < N_)
                    *(__half2*)&g_Hh[((size_t)w*N_ + rA)*64 + cout0] = __floats2half2_rn(c0, c1);
                if (rB < N_)
                    *(__half2*)&g_Hh[((size_t)w*N_ + rB)*64 + cout0] = __floats2half2_rn(c2, c3);
            }
        }
    }
}

// ---------------- launch -----------------------------------------------------
extern "C" void kernel_launch(void* const* d_in, const int* in_sizes, int n_in,
                              void* d_out, int out_size) {
    const float* x  = (const float*)d_in[0];
    const int*   ei = (const int*)  d_in[1];
    const float* ew = (const float*)d_in[2];

    WPtrs p;
    if (in_sizes[5] == 1024) {
        int idx = 3;
        for (int t = 0; t < 4; t++) {
            p.sw[t] = (const float*)d_in[idx++];
            p.sb[t] = (const float*)d_in[idx++];
            p.gw[t] = (const float*)d_in[idx++];
            p.gb[t] = (const float*)d_in[idx++];
        }
    } else {
        int idx = 3;
        for (int t = 0; t < 4; t++) {
            p.sw[t] = (const float*)d_in[idx++];
            p.sb[t] = (const float*)d_in[idx++];
        }
        for (int t = 0; t < 4; t++) {
            p.gw[t] = (const float*)d_in[idx++];
            p.gb[t] = (const float*)d_in[idx++];
        }
    }
    const float* gw = (const float*)d_in[19];
    const float* gb = (const float*)d_in[20];
    float* out = (float*)d_out;

    static cudaStream_t s2 = nullptr;
    static cudaEvent_t evA = nullptr, evB = nullptr;
    static int* degPtr = nullptr;
    static int* bhistPtr = nullptr;
    if (!s2) {
        cudaFuncSetAttribute(incep_mma_kernel,
                             cudaFuncAttributeMaxDynamicSharedMemorySize, SMEM_BYTES);
        cudaStreamCreateWithFlags(&s2, cudaStreamNonBlocking);
        cudaEventCreateWithFlags(&evA, cudaEventDisableTiming);
        cudaEventCreateWithFlags(&evB, cudaEventDisableTiming);
        cudaGetSymbolAddress((void**)&degPtr, g_deg);
        cudaGetSymbolAddress((void**)&bhistPtr, g_bhist);
    }

    // fork: CSR build + degree sort on s2, inception chain on main stream
    cudaEventRecord(evA, 0);
    cudaStreamWaitEvent(s2, evA, 0);

    cudaMemsetAsync(degPtr, 0, W_*N_*sizeof(int), s2);
    cudaMemsetAsync(bhistPtr, 0, 64*sizeof(int), s2);
    hist_kernel<<<(W_*E_/4 + 255)/256, 256, 0, s2>>>(ei);
    scan_kernel<<<W_, 512, 0, s2>>>();
    place_kernel<<<(W_*E_/4 + 255)/256, 256, 0, s2>>>(ei, ew);
    bhist_kernel<<<(W_*N_ + 255)/256, 256, 0, s2>>>();
    bscan_kernel<<<1, 64, 0, s2>>>();
    bplace_kernel<<<(W_*N_ + 255)/256, 256, 0, s2>>>();
    cudaEventRecord(evB, s2);

    prep_kernel<<<(7*128*64 + 255)/256, 256>>>(p);
    prep_gw_kernel<<<(2*12*8*4*32 + 255)/256, 256>>>(gw);
    pack_x_kernel<<<(W_*N_*8 + 255)/256, 256>>>((const float4*)x);
    incep_mma_kernel<<<N_/16, 256, SMEM_BYTES>>>();

    // join
    cudaStreamWaitEvent(0, evB, 0);

    for (int hop = 0; hop < 2; hop++) {
        agg_kernel<<<W_*N_*8/256, 256>>>();
        gemm_mma_kernel<<<dim3((N_ + 255)/256, W_), 256>>>(gb, hop, x,
                                                           hop == 1 ? out : nullptr);
    }
}

// round 16
// speedup vs baseline: 1.4749x; 1.1685x over previous
#include <cuda_runtime.h>
#include <cuda_fp16.h>
#include <cstdint>

#define W_ 12
#define N_ 20000
#define C_ 64
#define E_ 320000
#define TOT (W_*N_*C_)   // 15,360,000
typedef unsigned long long ull;
typedef unsigned int uint;

// ---------------- scratch (device globals) ----------------------------------
__device__ __align__(128) __half g_WpH[7*128*64];          // inception weights, plain [t][n][64]
__device__ __align__(128) __half g_XpH[(size_t)W_*N_*64];  // x rows fp16, plain [(w,n)][64]
__device__ __align__(128) ull    g_Gwp[2*12*8*4*32];       // gcn weights [(hop,w)][nt][ks][lane]
__device__ __align__(128) float  g_bc[128];
__device__ __align__(128) __half g_Hh [TOT];               // h buffer, fp16 channel-order (W,N,C)
__device__ __align__(128) uint   g_AggU[(size_t)W_*N_*32]; // aggregated h, fp16 MMA-A packed
__device__ int  g_deg   [W_*N_];
__device__ int  g_rowptr[W_*N_];
__device__ int  g_cur   [W_*N_];
__device__ int2 g_edge  [W_*E_];   // {src, wt bits}

struct WPtrs {
    const float* sw[4]; const float* sb[4];
    const float* gw[4]; const float* gb[4];
};

// ---------------- helpers ----------------------------------------------------
__device__ __forceinline__ uint pack_h2(float a, float b) {
    __half2 h = __floats2half2_rn(a, b);
    return *(uint*)&h;
}
__device__ __forceinline__ void mma_f16(float (&c)[4], uint a0, uint a1, uint a2, uint a3,
                                        uint b0, uint b1) {
    asm volatile(
        "mma.sync.aligned.m16n8k16.row.col.f32.f16.f16.f32 "
        "{%0,%1,%2,%3}, {%4,%5,%6,%7}, {%8,%9}, {%0,%1,%2,%3};\n"
        : "+f"(c[0]), "+f"(c[1]), "+f"(c[2]), "+f"(c[3])
        : "r"(a0), "r"(a1), "r"(a2), "r"(a3), "r"(b0), "r"(b1));
}
__device__ __forceinline__ void ldm_x4(uint& r0, uint& r1, uint& r2, uint& r3, uint a) {
    asm volatile("ldmatrix.sync.aligned.m8n8.x4.shared.b16 {%0,%1,%2,%3}, [%4];"
        : "=r"(r0), "=r"(r1), "=r"(r2), "=r"(r3) : "r"(a));
}
__device__ __forceinline__ void ldm_x2(uint& r0, uint& r1, uint a) {
    asm volatile("ldmatrix.sync.aligned.m8n8.x2.shared.b16 {%0,%1}, [%2];"
        : "=r"(r0), "=r"(r1) : "r"(a));
}
__device__ __forceinline__ void cpasync16(void* sdst, const void* gsrc) {
    uint s = (uint)__cvta_generic_to_shared(sdst);
    asm volatile("cp.async.ca.shared.global [%0], [%1], 16;" :: "r"(s), "l"(gsrc));
}
__device__ __forceinline__ void cp_commit() { asm volatile("cp.async.commit_group;"); }
__device__ __forceinline__ void cp_wait0()  { asm volatile("cp.async.wait_group 0;"); }
__device__ __forceinline__ float elu1(float v) { return v > 0.f ? v : expm1f(v); }
// L1-bypass 16B gather (random rows: ~0% L1 hit, avoid allocation/thrash)
__device__ __forceinline__ uint4 ldg_cg4(const uint4* p) {
    uint4 v;
    asm volatile("ld.global.cg.v4.u32 {%0,%1,%2,%3}, [%4];"
        : "=r"(v.x), "=r"(v.y), "=r"(v.z), "=r"(v.w) : "l"(p));
    return v;
}

// ---------------- K0: build plain fp16 inception weights + bias --------------
__global__ void prep_kernel(WPtrs p) {
    int gid = blockIdx.x * blockDim.x + threadIdx.x;
    if (gid < 7*128*64) {
        int t   = gid >> 13;           // 128*64 = 8192
        int rem = gid & 8191;
        int n   = rem >> 6, c = rem & 63;
        int kw  = n >> 5, half = (n >> 4) & 1, ch = n & 15, k = 2*kw + 1;
        int tt  = t - 3 + kw;
        float v = 0.f;
        if (tt >= 0 && tt < k)
            v = (half ? p.gw[kw] : p.sw[kw])[(ch*64 + c)*k + tt];
        g_WpH[gid] = __float2half(v);
    }
    if (gid < 128) {
        int j = gid;
        int kw = j >> 5; int half = (j >> 4) & 1; int ch = j & 15;
        g_bc[j] = half ? p.gb[kw][ch] : p.sb[kw][ch];
    }
}

// ---------------- K0c: pack gcn weights as MMA B-fragments -------------------
__global__ void prep_gw_kernel(const float* __restrict__ gw) {
    int gid = blockIdx.x*256 + threadIdx.x;
    if (gid >= 2*12*8*4*32) return;
    int lane = gid & 31;
    int ks   = (gid >> 5) & 3;
    int nt   = (gid >> 7) & 7;
    int rest = gid >> 10;            // hop*12 + w
    int n = nt*8 + (lane >> 2);
    int q = lane & 3;
    int k0 = ks*16 + 2*q;
    const float* Wb = gw + (size_t)rest*64*64;
    float v0 = Wb[(k0    )*64 + n];
    float v1 = Wb[(k0 + 1)*64 + n];
    float v2 = Wb[(k0 + 8)*64 + n];
    float v3 = Wb[(k0 + 9)*64 + n];
    g_Gwp[gid] = (ull)pack_h2(v0, v1) | ((ull)pack_h2(v2, v3) << 32);
}

// ---------------- K0b: pack x into plain fp16 rows ---------------------------
__global__ void pack_x_kernel(const float4* __restrict__ x4) {
    int gid = blockIdx.x*256 + threadIdx.x;
    if (gid >= W_*N_*8) return;
    int row = gid >> 3, c = gid & 7;
    float4 f0 = x4[(size_t)row*16 + c*2];
    float4 f1 = x4[(size_t)row*16 + c*2 + 1];
    uint4 o;
    o.x = pack_h2(f0.x, f0.y); o.y = pack_h2(f0.z, f0.w);
    o.z = pack_h2(f1.x, f1.y); o.w = pack_h2(f1.z, f1.w);
    ((uint4*)g_XpH)[(size_t)row*8 + c] = o;
}

// ---------------- K1: inception via fp16 mma + ldmatrix ----------------------
#define XROWB 144
#define XS_BYTES (18*16*XROWB)       // 41472
#define WS_BYTES (128*XROWB)         // 18432
#define SMEM_BYTES (XS_BYTES + 2*WS_BYTES)

__global__ void __launch_bounds__(256, 2) incep_mma_kernel() {
    extern __shared__ char sm[];
    char* Xs = sm;                    // [wi(18)][nloc(16)] rows
    char* Ws = sm + XS_BYTES;         // [2][n(128)] rows

    int tid = threadIdx.x;
    int n0  = blockIdx.x * 16;

    {
        const int zl[6] = {0,1,2,15,16,17};
        for (int idx = tid; idx < 6*16*9; idx += 256) {
            int r = idx / 9, c = idx - r*9;
            int wi = zl[r >> 4], nloc = r & 15;
            ((uint4*)(Xs + (wi*16 + nloc)*XROWB))[c] = make_uint4(0,0,0,0);
        }
    }
    for (int idx = tid; idx < 12*16*8; idx += 256) {
        int c = idx & 7, row = idx >> 3;
        int wrow = row >> 4, nloc = row & 15;
        cpasync16(Xs + ((wrow+3)*16 + nloc)*XROWB + c*16,
                  g_XpH + ((size_t)(wrow*N_ + n0 + nloc))*64 + c*8);
    }
    for (int idx = tid; idx < 128*8; idx += 256) {
        int c = idx & 7, n = idx >> 3;
        cpasync16(Ws + n*XROWB + c*16, g_WpH + ((size_t)n)*64 + c*8);
    }
    cp_commit();
    cp_wait0();
    __syncthreads();

    int lane = tid & 31, wid = tid >> 5;
    int mg = wid >> 1, par = wid & 1;
    int g = lane >> 2, q = lane & 3;

    uint xsB = (uint)__cvta_generic_to_shared(Xs);
    uint wsB = (uint)__cvta_generic_to_shared(Ws);
    uint aA0 = xsB + (lane & 15)*XROWB + (lane >> 4)*16;
    uint bA0 = wsB + (lane & 7)*XROWB + ((lane >> 3) & 1)*16;

    float acc[3][8][4];
    #pragma unroll
    for (int j = 0; j < 3; j++)
        #pragma unroll
        for (int u = 0; u < 8; u++)
            #pragma unroll
            for (int c = 0; c < 4; c++) acc[j][u][c] = 0.f;

    for (int t = 0; t < 7; t++) {
        if (t < 6) {
            char* Wn = Ws + ((t+1)&1)*WS_BYTES;
            for (int idx = tid; idx < 128*8; idx += 256) {
                int c = idx & 7, n = idx >> 3;
                cpasync16(Wn + n*XROWB + c*16, g_WpH + ((size_t)((t+1)*128 + n))*64 + c*8);
            }
            cp_commit();
        }
        uint wB = bA0 + (t&1)*WS_BYTES;
        uint aB = aA0 + (3*mg + t)*(16*XROWB);

        #pragma unroll
        for (int ks = 0; ks < 4; ks++) {
            uint a0[3], a1[3], a2[3], a3[3];
            #pragma unroll
            for (int j = 0; j < 3; j++)
                ldm_x4(a0[j], a1[j], a2[j], a3[j], aB + j*(16*XROWB) + ks*32);
            #pragma unroll
            for (int u = 0; u < 8; u++) {
                int nt = 2*u + par;
                int kw = nt >> 2;
                if (t >= 3-kw && t <= 3+kw) {
                    uint b0, b1;
                    ldm_x2(b0, b1, wB + nt*(8*XROWB) + ks*32);
                    mma_f16(acc[0][u], a0[0], a1[0], a2[0], a3[0], b0, b1);
                    mma_f16(acc[1][u], a0[1], a1[1], a2[1], a3[1], b0, b1);
                    mma_f16(acc[2][u], a0[2], a1[2], a2[2], a3[2], b0, b1);
                }
            }
        }
        if (t < 6) cp_wait0();
        __syncthreads();
    }

    #pragma unroll
    for (int j = 0; j < 3; j++) {
        int w = 3*mg + j;
        #pragma unroll
        for (int us = 0; us < 8; us += 2) {
            int nts = 2*us + par;
            float2 bs = *(const float2*)&g_bc[nts*8 + 2*q];
            float2 bg = *(const float2*)&g_bc[(nts+2)*8 + 2*q];
            float s0 = acc[j][us][0] + bs.x, s1 = acc[j][us][1] + bs.y;
            float s2 = acc[j][us][2] + bs.x, s3 = acc[j][us][3] + bs.y;
            float g0 = acc[j][us+1][0] + bg.x, g1 = acc[j][us+1][1] + bg.y;
            float g2 = acc[j][us+1][2] + bg.x, g3 = acc[j][us+1][3] + bg.y;
            float o0 = fmaxf(s0, 0.f) * (1.f/(1.f + __expf(-g0)));
            float o1 = fmaxf(s1, 0.f) * (1.f/(1.f + __expf(-g1)));
            float o2 = fmaxf(s2, 0.f) * (1.f/(1.f + __expf(-g2)));
            float o3 = fmaxf(s3, 0.f) * (1.f/(1.f + __expf(-g3)));
            int kw = nts >> 2;
            int cout = kw*16 + par*8 + 2*q;
            *(__half2*)&g_Hh[((size_t)w*N_ + n0 + g    )*64 + cout] = __floats2half2_rn(o0, o1);
            *(__half2*)&g_Hh[((size_t)w*N_ + n0 + g + 8)*64 + cout] = __floats2half2_rn(o2, o3);
        }
    }
}

// ---------------- CSR build (once), 4 edges/thread ---------------------------
__global__ void hist_kernel(const int* __restrict__ ei) {
    int g = blockIdx.x*blockDim.x + threadIdx.x;
    if (g >= W_*E_/4) return;
    int w  = g / (E_/4);
    int e4 = (g - w*(E_/4))*4;
    int4 d = *(const int4*)&ei[(size_t)(2*w+1)*E_ + e4];
    atomicAdd(&g_deg[w*N_ + d.x], 1);
    atomicAdd(&g_deg[w*N_ + d.y], 1);
    atomicAdd(&g_deg[w*N_ + d.z], 1);
    atomicAdd(&g_deg[w*N_ + d.w], 1);
}

__global__ void __launch_bounds__(512) scan_kernel() {
    __shared__ int wsum[16];
    int w = blockIdx.x;
    int t = threadIdx.x, lane = t & 31, wid = t >> 5;
    const int* deg = g_deg + w*N_;
    int base = t * 40;
    int s = 0;
    for (int k = 0; k < 40; k++) {
        int idx = base + k;
        if (idx < N_) s += deg[idx];
    }
    int v = s;
    #pragma unroll
    for (int d = 1; d < 32; d <<= 1) {
        int o = __shfl_up_sync(0xffffffffu, v, d);
        if (lane >= d) v += o;
    }
    if (lane == 31) wsum[wid] = v;
    __syncthreads();
    if (t == 0) {
        int r = 0;
        #pragma unroll
        for (int qq = 0; qq < 16; qq++) { int xq = wsum[qq]; wsum[qq] = r; r += xq; }
    }
    __syncthreads();
    int run = wsum[wid] + (v - s);
    for (int k = 0; k < 40; k++) {
        int idx = base + k;
        if (idx < N_) {
            int d = deg[idx];
            g_rowptr[w*N_ + idx] = run;
            g_cur   [w*N_ + idx] = run;
            run += d;
        }
    }
}

__global__ void place_kernel(const int* __restrict__ ei, const float* __restrict__ ewt) {
    int g = blockIdx.x*blockDim.x + threadIdx.x;
    if (g >= W_*E_/4) return;
    int w  = g / (E_/4);
    int e4 = (g - w*(E_/4))*4;
    int4   s = *(const int4*)  &ei [(size_t)(2*w)  *E_ + e4];
    int4   d = *(const int4*)  &ei [(size_t)(2*w+1)*E_ + e4];
    float4 t = *(const float4*)&ewt[(size_t)w*E_ + e4];
    int2* eb = g_edge + (size_t)w*E_;
    int* cur = g_cur + w*N_;
    int p0 = atomicAdd(&cur[d.x], 1);
    int p1 = atomicAdd(&cur[d.y], 1);
    int p2 = atomicAdd(&cur[d.z], 1);
    int p3 = atomicAdd(&cur[d.w], 1);
    eb[p0] = make_int2(s.x, __float_as_int(t.x));
    eb[p1] = make_int2(s.y, __float_as_int(t.y));
    eb[p2] = make_int2(s.z, __float_as_int(t.z));
    eb[p3] = make_int2(s.w, __float_as_int(t.w));
}

// ---------------- K4: gather-aggregate, batch-16 shuffle-broadcast ----------
__global__ void __launch_bounds__(256) agg_kernel() {
    int gid = blockIdx.x*256 + threadIdx.x;
    int q  = gid & 7;           // 8-channel slice
    int wn = gid >> 3;
    int w  = wn / N_;
    int lane = threadIdx.x & 31;
    uint gmask = 0xffu << (lane & 24);

    int beg = g_rowptr[wn];
    int deg = g_deg[wn];
    const int2*  ed = g_edge + (size_t)w*E_;
    const uint4* Hb = (const uint4*)g_Hh + (size_t)w*N_*8 + q;

    float a0=0.f,a1=0.f,a2=0.f,a3=0.f,a4=0.f,a5=0.f,a6=0.f,a7=0.f;
    for (int base = 0; base < deg; base += 16) {
        int lim = deg - base;
        int2 pr0 = make_int2(0, 0), pr1 = make_int2(0, 0);
        if (q     < lim) pr0 = ed[beg + base + q];
        if (q + 8 < lim) pr1 = ed[beg + base + 8 + q];
        int m = lim < 16 ? lim : 16;
        #pragma unroll
        for (int j = 0; j < 16; j++) {
            if (j < m) {
                int   src = __shfl_sync(gmask, j < 8 ? pr0.x : pr1.x, j & 7, 8);
                float wt  = __int_as_float(__shfl_sync(gmask, j < 8 ? pr0.y : pr1.y, j & 7, 8));
                uint4 v = ldg_cg4(Hb + (size_t)src*8);
                const __half2* hp = (const __half2*)&v;
                float2 f0 = __half22float2(hp[0]);
                float2 f1 = __half22float2(hp[1]);
                float2 f2 = __half22float2(hp[2]);
                float2 f3 = __half22float2(hp[3]);
                a0 = fmaf(wt, f0.x, a0); a1 = fmaf(wt, f0.y, a1);
                a2 = fmaf(wt, f1.x, a2); a3 = fmaf(wt, f1.y, a3);
                a4 = fmaf(wt, f2.x, a4); a5 = fmaf(wt, f2.y, a5);
                a6 = fmaf(wt, f3.x, a6); a7 = fmaf(wt, f3.y, a7);
            }
        }
    }
    int s = q >> 1, odd = q & 1;
    uint* o = g_AggU + (size_t)wn*32;
    o[(s*4 + 0)*2 + odd] = pack_h2(a0, a1);
    o[(s*4 + 1)*2 + odd] = pack_h2(a2, a3);
    o[(s*4 + 2)*2 + odd] = pack_h2(a4, a5);
    o[(s*4 + 3)*2 + odd] = pack_h2(a6, a7);
}

// ---------------- K5: tensor-core gemm + bias + ELU (+residual) -------------
__global__ void __launch_bounds__(256) gemm_mma_kernel(const float* __restrict__ gb, int hop,
                                                       const float* __restrict__ x,
                                                       float* __restrict__ out) {
    int w = blockIdx.y;
    int wid = threadIdx.x >> 5, lane = threadIdx.x & 31;
    int g = lane >> 2, q = lane & 3;
    int n0 = blockIdx.x*256 + wid*32;
    if (n0 >= N_) return;

    const ull* A  = (const ull*)g_AggU + (size_t)w*N_*16;
    const ull* Wm = g_Gwp + ((size_t)(hop*W_ + w))*8*4*32;
    const float* bias = gb + (size_t)(hop*W_ + w)*64;

    float acc[2][8][4];
    #pragma unroll
    for (int nt = 0; nt < 8; nt++) {
        float2 bv = *(const float2*)&bias[nt*8 + 2*q];
        #pragma unroll
        for (int mt = 0; mt < 2; mt++) {
            acc[mt][nt][0] = bv.x; acc[mt][nt][1] = bv.y;
            acc[mt][nt][2] = bv.x; acc[mt][nt][3] = bv.y;
        }
    }

    int r0 = n0 + g, r1 = n0 + g + 8, r2 = n0 + 16 + g, r3 = n0 + 24 + g;
    #pragma unroll
    for (int ks = 0; ks < 4; ks++) {
        int kk = ks*4 + q;
        ull v0 = (r0 < N_) ? A[(size_t)r0*16 + kk] : 0ull;
        ull v1 = (r1 < N_) ? A[(size_t)r1*16 + kk] : 0ull;
        ull v2 = (r2 < N_) ? A[(size_t)r2*16 + kk] : 0ull;
        ull v3 = (r3 < N_) ? A[(size_t)r3*16 + kk] : 0ull;
        uint a00 = (uint)v0, a02 = (uint)(v0 >> 32);
        uint a01 = (uint)v1, a03 = (uint)(v1 >> 32);
        uint a10 = (uint)v2, a12 = (uint)(v2 >> 32);
        uint a11 = (uint)v3, a13 = (uint)(v3 >> 32);
        #pragma unroll
        for (int nt = 0; nt < 8; nt++) {
            ull bw = Wm[(nt*4 + ks)*32 + lane];
            uint b0 = (uint)bw, b1 = (uint)(bw >> 32);
            mma_f16(acc[0][nt], a00, a01, a02, a03, b0, b1);
            mma_f16(acc[1][nt], a10, a11, a12, a13, b0, b1);
        }
    }

    #pragma unroll
    for (int mt = 0; mt < 2; mt++) {
        int rA = n0 + mt*16 + g, rB = rA + 8;
        #pragma unroll
        for (int nt = 0; nt < 8; nt++) {
            float c0 = elu1(acc[mt][nt][0]);
            float c1 = elu1(acc[mt][nt][1]);
            float c2 = elu1(acc[mt][nt][2]);
            float c3 = elu1(acc[mt][nt][3]);
            int cout0 = nt*8 + 2*q;
            if (out) {
                if (rA < N_) {
                    size_t oi = ((size_t)w*N_ + rA)*64 + cout0;
                    float2 xv = *(const float2*)&x[oi];
                    *(float2*)&out[oi] = make_float2(c0 + xv.x, c1 + xv.y);
                }
                if (rB < N_) {
                    size_t oi = ((size_t)w*N_ + rB)*64 + cout0;
                    float2 xv = *(const float2*)&x[oi];
                    *(float2*)&out[oi] = make_float2(c2 + xv.x, c3 + xv.y);
                }
            } else {
                if (rA < N_)
                    *(__half2*)&g_Hh[((size_t)w*N_ + rA)*64 + cout0] = __floats2half2_rn(c0, c1);
                if (rB < N_)
                    *(__half2*)&g_Hh[((size_t)w*N_ + rB)*64 + cout0] = __floats2half2_rn(c2, c3);
            }
        }
    }
}

// ---------------- launch -----------------------------------------------------
extern "C" void kernel_launch(void* const* d_in, const int* in_sizes, int n_in,
                              void* d_out, int out_size) {
    const float* x  = (const float*)d_in[0];
    const int*   ei = (const int*)  d_in[1];
    const float* ew = (const float*)d_in[2];

    WPtrs p;
    if (in_sizes[5] == 1024) {
        int idx = 3;
        for (int t = 0; t < 4; t++) {
            p.sw[t] = (const float*)d_in[idx++];
            p.sb[t] = (const float*)d_in[idx++];
            p.gw[t] = (const float*)d_in[idx++];
            p.gb[t] = (const float*)d_in[idx++];
        }
    } else {
        int idx = 3;
        for (int t = 0; t < 4; t++) {
            p.sw[t] = (const float*)d_in[idx++];
            p.sb[t] = (const float*)d_in[idx++];
        }
        for (int t = 0; t < 4; t++) {
            p.gw[t] = (const float*)d_in[idx++];
            p.gb[t] = (const float*)d_in[idx++];
        }
    }
    const float* gw = (const float*)d_in[19];
    const float* gb = (const float*)d_in[20];
    float* out = (float*)d_out;

    static cudaStream_t s2 = nullptr;
    static cudaEvent_t evA = nullptr, evB = nullptr;
    static int* degPtr = nullptr;
    if (!s2) {
        cudaFuncSetAttribute(incep_mma_kernel,
                             cudaFuncAttributeMaxDynamicSharedMemorySize, SMEM_BYTES);
        cudaStreamCreateWithFlags(&s2, cudaStreamNonBlocking);
        cudaEventCreateWithFlags(&evA, cudaEventDisableTiming);
        cudaEventCreateWithFlags(&evB, cudaEventDisableTiming);
        cudaGetSymbolAddress((void**)&degPtr, g_deg);
    }

    // fork: CSR build (+ gcn weight pack) on s2, inception chain on main stream
    cudaEventRecord(evA, 0);
    cudaStreamWaitEvent(s2, evA, 0);

    cudaMemsetAsync(degPtr, 0, W_*N_*sizeof(int), s2);
    prep_gw_kernel<<<(2*12*8*4*32 + 255)/256, 256, 0, s2>>>(gw);
    hist_kernel<<<(W_*E_/4 + 255)/256, 256, 0, s2>>>(ei);
    scan_kernel<<<W_, 512, 0, s2>>>();
    place_kernel<<<(W_*E_/4 + 255)/256, 256, 0, s2>>>(ei, ew);
    cudaEventRecord(evB, s2);

    prep_kernel<<<(7*128*64 + 255)/256, 256>>>(p);
    pack_x_kernel<<<(W_*N_*8 + 255)/256, 256>>>((const float4*)x);
    incep_mma_kernel<<<N_/16, 256, SMEM_BYTES>>>();

    // join
    cudaStreamWaitEvent(0, evB, 0);

    for (int hop = 0; hop < 2; hop++) {
        agg_kernel<<<W_*N_*8/256, 256>>>();
        gemm_mma_kernel<<<dim3((N_ + 255)/256, W_), 256>>>(gb, hop, x,
                                                           hop == 1 ? out : nullptr);
    }
}